// round 4
// baseline (speedup 1.0000x reference)
#include <cuda_runtime.h>
#include <cuda_bf16.h>
#include <cstdint>

// ============================================================================
// Hyperbolic averaged Hausdorff loss via mma.sync bf16 (sm_80 path; the build
// targets plain sm_103 so tcgen05 is unavailable).
//
// dot(X_i,Y_j) via bf16 hi/lo split, K=48:
//   A_i = [xh(16) | xl(16) | xh(16)],  B_j = [yh(16) | yh(16) | yl(16)]
//   => acc = xh.yh + xl.yh + xh.yl  ~= x.y   (err ~2^-18)
// Per-point params precomputed as float4 (n2, inv, -2inv, n2*inv):
//   t = sqdist*invy = fma2(dot2, ay2, fma2(xn2, iy2, by2))   (row mins)
//   s = sqdist*invx = fma2(dot2, ax2, fma2(yn2, ix2, bx2))   (col mins)
// arcosh is monotone => mins commute; finalize applies arcosh + mean and the
// last finished block does the final 128-way sum (g_done counter).
// ============================================================================

#define NPTS 16384

__device__ float4 g_px[NPTS], g_py[NPTS];
__device__ int    g_rowmin[NPTS], g_colmin[NPTS];
__device__ float  g_part[128];
__device__ int    g_done;
__device__ __nv_bfloat16 g_A[NPTS * 48];
__device__ __nv_bfloat16 g_B[NPTS * 48];

__device__ __forceinline__ uint32_t smem_u32(const void* p) {
    uint32_t a;
    asm("{ .reg .u64 t; cvta.to.shared.u64 t, %1; cvt.u32.u64 %0, t; }"
        : "=r"(a) : "l"(p));
    return a;
}
#define SMEM_SWZ(o) ((o) ^ ((((o) >> 3) & 0x70)))

#define LDSM4(r, addr)                                                      \
    asm volatile("ldmatrix.sync.aligned.m8n8.x4.shared.b16 "                \
                 "{%0,%1,%2,%3}, [%4];"                                     \
                 : "=r"((r)[0]), "=r"((r)[1]), "=r"((r)[2]), "=r"((r)[3])   \
                 : "r"(addr))

#define MMA16816(d, a, b0, b1)                                              \
    asm volatile("mma.sync.aligned.m16n8k16.row.col.f32.bf16.bf16.f32 "     \
                 "{%0,%1,%2,%3}, {%4,%5,%6,%7}, {%8,%9}, {%0,%1,%2,%3};"    \
                 : "+f"((d)[0]), "+f"((d)[1]), "+f"((d)[2]), "+f"((d)[3])   \
                 : "r"((a)[0]), "r"((a)[1]), "r"((a)[2]), "r"((a)[3]),      \
                   "r"(b0), "r"(b1))

typedef unsigned long long ull;
__device__ __forceinline__ ull pk2f(float lo, float hi) {
    ull r;
    asm("mov.b64 %0, {%1, %2};" : "=l"(r) : "f"(lo), "f"(hi));
    return r;
}
__device__ __forceinline__ void upk2(ull v, float& lo, float& hi) {
    asm("mov.b64 {%0, %1}, %2;" : "=f"(lo), "=f"(hi) : "l"(v));
}
// d = a*b + c   (packed f32x2)
#define FMA2(d, a, b, c) \
    asm("fma.rn.f32x2 %0, %1, %2, %3;" : "=l"(d) : "l"(a), "l"(b), "l"(c))

// ---------------------------------------------------------------- prep kernel
union BU { __nv_bfloat16 b; unsigned short u; };
__device__ __forceinline__ unsigned short bfu(float x) {
    BU t; t.b = __float2bfloat16(x); return t.u;
}
__device__ __forceinline__ float bff(unsigned short u) {
    BU t; t.u = u; return __bfloat162float(t.b);
}

__device__ __forceinline__ void split_store(const float* src, int idx,
                                            __nv_bfloat16* dst, bool isA,
                                            float4* par, int* mn) {
    float v[16];
    const float4* p = (const float4*)(src + (size_t)idx * 16);
    float4 q0 = p[0], q1 = p[1], q2 = p[2], q3 = p[3];
    v[0]=q0.x; v[1]=q0.y; v[2]=q0.z; v[3]=q0.w;
    v[4]=q1.x; v[5]=q1.y; v[6]=q1.z; v[7]=q1.w;
    v[8]=q2.x; v[9]=q2.y; v[10]=q2.z; v[11]=q2.w;
    v[12]=q3.x; v[13]=q3.y; v[14]=q3.z; v[15]=q3.w;
    float s = 0.f;
#pragma unroll
    for (int d = 0; d < 16; d++) s += v[d] * v[d];
    float inv = 1.0f / (1.0f - s);
    par[idx] = make_float4(s, inv, -2.0f * inv, s * inv);
    mn[idx]  = 0x7f800000;

    unsigned short hi[16], lo[16];
#pragma unroll
    for (int d = 0; d < 16; d++) {
        hi[d] = bfu(v[d]);
        lo[d] = bfu(v[d] - bff(hi[d]));
    }
    uint32_t w[24];
#pragma unroll
    for (int k = 0; k < 8; k++) {
        uint32_t hp = (uint32_t)hi[2*k] | ((uint32_t)hi[2*k+1] << 16);
        uint32_t lp = (uint32_t)lo[2*k] | ((uint32_t)lo[2*k+1] << 16);
        w[k]      = hp;
        w[8 + k]  = isA ? lp : hp;
        w[16 + k] = isA ? hp : lp;
    }
    uint4* d4 = (uint4*)(dst + (size_t)idx * 48);
#pragma unroll
    for (int c = 0; c < 6; c++)
        d4[c] = make_uint4(w[4*c], w[4*c+1], w[4*c+2], w[4*c+3]);
}

__global__ void prep_kernel(const float* __restrict__ X,
                            const float* __restrict__ Y, int N, int M) {
    int idx = blockIdx.x * 256 + threadIdx.x;
    if (idx == 0) g_done = 0;
    if (idx < N) split_store(X, idx, g_A, true,  g_px, g_rowmin);
    if (idx < M) split_store(Y, idx, g_B, false, g_py, g_colmin);
}

// ---------------------------------------------------------------- pair kernel
__global__ void __launch_bounds__(256, 2) pair_mma_kernel() {
    __shared__ __align__(16) char sA[128 * 128];
    __shared__ __align__(16) char sB[128 * 128];
    __shared__ float4 s_px[128], s_py[128];
    __shared__ float rowpart[2][128];
    __shared__ float colpart[4][128];

    const int tid  = threadIdx.x;
    const int wid  = tid >> 5;
    const int lane = tid & 31;
    const int i0   = blockIdx.y * 128;
    const int j0   = blockIdx.x * 128;

    // ---- load tiles: rows packed at 96B in gmem, 128B pitch + SW128 in smem
    {
        const uint4* Ag = (const uint4*)g_A + (size_t)i0 * 6;
        const uint4* Bg = (const uint4*)g_B + (size_t)j0 * 6;
#pragma unroll
        for (int k = tid; k < 768; k += 256) {
            int r = k / 6, c = k - 6 * r;
            *(uint4*)(sA + SMEM_SWZ(r * 128 + c * 16)) = Ag[k];
            *(uint4*)(sB + SMEM_SWZ(r * 128 + c * 16)) = Bg[k];
        }
    }
    if (tid < 128) {
        s_px[tid] = g_px[i0 + tid];
        s_py[tid] = g_py[j0 + tid];
    }
    __syncthreads();

    const uint32_t sAb = smem_u32(sA);
    const uint32_t sBb = smem_u32(sB);
    const int wr = wid & 3;          // warp row block: 32 i-rows
    const int wc = wid >> 2;         // warp col block: 64 j-cols
    const int lr = lane & 15;
    const int lc = lane >> 4;
    const float INF = __int_as_float(0x7f800000);

    // ---- A fragments hoisted (used by both column halves)
    uint32_t afr[3][2][4];
#pragma unroll
    for (int ks = 0; ks < 3; ks++)
#pragma unroll
        for (int mt = 0; mt < 2; mt++) {
            int row = 32 * wr + 16 * mt + lr;
            LDSM4(afr[ks][mt], sAb + SMEM_SWZ(row * 128 + ks * 32 + lc * 16));
        }

    // ---- per-row packed constants (rows r = 32wr + 16mt + 8rr + lane>>2)
    ull xn2[4], ix2[4], ax2[4], bx2[4];
#pragma unroll
    for (int mt = 0; mt < 2; mt++)
#pragma unroll
        for (int rr = 0; rr < 2; rr++) {
            int k = 2 * mt + rr;
            float4 p = s_px[32 * wr + 16 * mt + 8 * rr + (lane >> 2)];
            xn2[k] = pk2f(p.x, p.x);
            ix2[k] = pk2f(p.y, p.y);
            ax2[k] = pk2f(p.z, p.z);
            bx2[k] = pk2f(p.w, p.w);
        }

    float rmin[4] = {INF, INF, INF, INF};

#pragma unroll
    for (int h = 0; h < 2; h++) {
        float acc[2][4][4];
#pragma unroll
        for (int mt = 0; mt < 2; mt++)
#pragma unroll
            for (int nt = 0; nt < 4; nt++)
#pragma unroll
                for (int e = 0; e < 4; e++) acc[mt][nt][e] = 0.0f;

#pragma unroll
        for (int ks = 0; ks < 3; ks++) {
            uint32_t b[2][4];
#pragma unroll
            for (int np = 0; np < 2; np++) {
                int row = 64 * wc + 32 * h + 16 * np + lr;
                LDSM4(b[np], sBb + SMEM_SWZ(row * 128 + ks * 32 + lc * 16));
            }
#pragma unroll
            for (int mt = 0; mt < 2; mt++)
#pragma unroll
                for (int nt = 0; nt < 4; nt++) {
                    int np = nt >> 1, od = nt & 1;
                    MMA16816(acc[mt][nt], afr[ks][mt], b[np][od], b[np][od+2]);
                }
        }

        // ---- epilogue: packed f32x2 fma, scalar mins (alu pipe)
        float cmin[8];
#pragma unroll
        for (int k = 0; k < 8; k++) cmin[k] = INF;

#pragma unroll
        for (int nt = 0; nt < 4; nt++) {
            int jj = 64 * wc + 32 * h + 8 * nt + 2 * (lane & 3);
            float4 f0 = s_py[jj], f1 = s_py[jj + 1];
            ull yn2 = pk2f(f0.x, f1.x);
            ull iy2 = pk2f(f0.y, f1.y);
            ull ay2 = pk2f(f0.z, f1.z);
            ull by2 = pk2f(f0.w, f1.w);
#pragma unroll
            for (int mt = 0; mt < 2; mt++) {
                const float* c = acc[mt][nt];
                ull d0 = pk2f(c[0], c[1]);
                ull d1 = pk2f(c[2], c[3]);
                ull u0, u1, t0, t1;
                FMA2(u0, xn2[2*mt],   iy2, by2);
                FMA2(t0, d0, ay2, u0);
                FMA2(u1, xn2[2*mt+1], iy2, by2);
                FMA2(t1, d1, ay2, u1);
                float tl, th;
                upk2(t0, tl, th);
                rmin[2*mt]   = fminf(rmin[2*mt],   fminf(tl, th));
                upk2(t1, tl, th);
                rmin[2*mt+1] = fminf(rmin[2*mt+1], fminf(tl, th));

                ull w0, w1, s0, s1;
                FMA2(w0, yn2, ix2[2*mt],   bx2[2*mt]);
                FMA2(s0, d0, ax2[2*mt], w0);
                FMA2(w1, yn2, ix2[2*mt+1], bx2[2*mt+1]);
                FMA2(s1, d1, ax2[2*mt+1], w1);
                float a0, a1, b0f, b1f;
                upk2(s0, a0, a1);
                upk2(s1, b0f, b1f);
                cmin[2*nt]   = fminf(cmin[2*nt],   fminf(a0, b0f));
                cmin[2*nt+1] = fminf(cmin[2*nt+1], fminf(a1, b1f));
            }
        }

        // reduce col-mins across row-lanes (xor 4, 8, 16), lanes 0..3 store
#pragma unroll
        for (int k = 0; k < 8; k++) {
            float v = cmin[k];
            v = fminf(v, __shfl_xor_sync(0xffffffffu, v, 4));
            v = fminf(v, __shfl_xor_sync(0xffffffffu, v, 8));
            v = fminf(v, __shfl_xor_sync(0xffffffffu, v, 16));
            if (lane < 4)
                colpart[wr][64*wc + 32*h + 8*(k >> 1) + 2*lane + (k & 1)] = v;
        }
    }

    // reduce row-mins across col-lanes (xor 1, 2)
#pragma unroll
    for (int k = 0; k < 4; k++) {
        float v = rmin[k];
        v = fminf(v, __shfl_xor_sync(0xffffffffu, v, 1));
        v = fminf(v, __shfl_xor_sync(0xffffffffu, v, 2));
        if ((lane & 3) == 0)
            rowpart[wc][32*wr + 16*(k >> 1) + 8*(k & 1) + (lane >> 2)] = v;
    }
    __syncthreads();

    if (tid < 128) {
        float rv = fminf(rowpart[0][tid], rowpart[1][tid]);
        atomicMin(&g_rowmin[i0 + tid], __float_as_int(fmaxf(rv, 0.0f)));
        float cv = fminf(fminf(colpart[0][tid], colpart[1][tid]),
                         fminf(colpart[2][tid], colpart[3][tid]));
        atomicMin(&g_colmin[j0 + tid], __float_as_int(fmaxf(cv, 0.0f)));
    }
}

// ---------------------------------------------------------------- finalize
__global__ void finalize_kernel(int N, int M, float* out) {
    __shared__ float red[256];
    __shared__ int   lastFlag;
    int  b     = blockIdx.x;
    bool isRow = (b < 64);
    int  idx   = (isRow ? b : b - 64) * 256 + threadIdx.x;
    float val  = 0.0f;
    int   lim  = isRow ? N : M;
    if (idx < lim) {
        float m   = fmaxf(__int_as_float(isRow ? g_rowmin[idx] : g_colmin[idx]),
                          0.0f);
        float inv = isRow ? g_px[idx].y : g_py[idx].y;
        float u   = fmaf(2.0f * m, inv, 1.0f);
        val       = logf(u + sqrtf(fmaxf(u * u - 1.0f, 0.0f)));
    }
    red[threadIdx.x] = val;
    __syncthreads();
    for (int s = 128; s > 0; s >>= 1) {
        if (threadIdx.x < s) red[threadIdx.x] += red[threadIdx.x + s];
        __syncthreads();
    }
    if (threadIdx.x == 0) {
        g_part[b] = red[0] * (isRow ? 1.0f / (float)N : 1.0f / (float)M);
        __threadfence();
        int t = atomicAdd(&g_done, 1);
        lastFlag = (t == 127);
    }
    __syncthreads();
    if (lastFlag) {
        red[threadIdx.x] = (threadIdx.x < 128) ? g_part[threadIdx.x] : 0.0f;
        __syncthreads();
        for (int s = 128; s > 0; s >>= 1) {
            if (threadIdx.x < s) red[threadIdx.x] += red[threadIdx.x + s];
            __syncthreads();
        }
        if (threadIdx.x == 0) out[0] = red[0];
    }
}

// ---------------------------------------------------------------- launch
extern "C" void kernel_launch(void* const* d_in, const int* in_sizes, int n_in,
                              void* d_out, int out_size) {
    const float* X = (const float*)d_in[0];
    const float* Y = (const float*)d_in[1];
    int N = in_sizes[0] / 16;
    int M = in_sizes[1] / 16;

    int mx = (N > M ? N : M);
    prep_kernel<<<(mx + 255) / 256, 256>>>(X, Y, N, M);

    dim3 grid(M / 128, N / 128);
    pair_mma_kernel<<<grid, 256>>>();

    finalize_kernel<<<128, 256>>>(N, M, (float*)d_out);
}

// round 5
// speedup vs baseline: 1.1828x; 1.1828x over previous
#include <cuda_runtime.h>
#include <cuda_bf16.h>
#include <cstdint>

// ============================================================================
// Hyperbolic averaged Hausdorff loss via tensor-core mma.sync (bf16).
// (build targets plain sm_103: tcgen05 unavailable; legacy HMMA path)
//
// dot with fp32-ish accuracy using a bf16 hi/lo split, K widened to fold the
// norm terms directly into the accumulator:
//   A_i cols: [xh(16) | xl(16) | xh(16) | xn_h, xn_l, 1, 1 | 0 x12]   (K=64)
//   B_j cols: [yh(16) | yh(16) | yl(16) | -.5, -.5, m_h, m_l | 0 x12]
//   where m = -yn/2.  =>  acc_ij = dot_ij - (xn_i + yn_j)/2
//   sqdist = -2*acc ; row-min of sqdist*invy = min_j acc*(-2*invy_j)
//            col-min of sqdist*invx = min_i acc*(-2*invx_i)
// arcosh monotone => mins commute; finalize applies arcosh, and the last
// finished finalize block performs the final 128-way sum (g_done counter).
// ============================================================================

#define NPTS 16384

__device__ float g_invx[NPTS], g_invy[NPTS];
__device__ int   g_rowmin[NPTS], g_colmin[NPTS];
__device__ float g_part[128];
__device__ int   g_done;
__device__ __nv_bfloat16 g_A[NPTS * 64];
__device__ __nv_bfloat16 g_B[NPTS * 64];

__device__ __forceinline__ uint32_t smem_u32(const void* p) {
    uint32_t a;
    asm("{ .reg .u64 t; cvta.to.shared.u64 t, %1; cvt.u32.u64 %0, t; }"
        : "=r"(a) : "l"(p));
    return a;
}
#define SMEM_SWZ(o) ((o) ^ ((((o) >> 3) & 0x70)))

#define LDSM4(r, addr)                                                      \
    asm volatile("ldmatrix.sync.aligned.m8n8.x4.shared.b16 "                \
                 "{%0,%1,%2,%3}, [%4];"                                     \
                 : "=r"((r)[0]), "=r"((r)[1]), "=r"((r)[2]), "=r"((r)[3])   \
                 : "r"(addr))

#define MMA16816(d, a, b0, b1)                                              \
    asm volatile("mma.sync.aligned.m16n8k16.row.col.f32.bf16.bf16.f32 "     \
                 "{%0,%1,%2,%3}, {%4,%5,%6,%7}, {%8,%9}, {%0,%1,%2,%3};"    \
                 : "+f"((d)[0]), "+f"((d)[1]), "+f"((d)[2]), "+f"((d)[3])   \
                 : "r"((a)[0]), "r"((a)[1]), "r"((a)[2]), "r"((a)[3]),      \
                   "r"(b0), "r"(b1))

// ---------------------------------------------------------------- prep kernel
union BU { __nv_bfloat16 b; unsigned short u; };
__device__ __forceinline__ unsigned short bfu(float x) {
    BU t; t.b = __float2bfloat16(x); return t.u;
}
__device__ __forceinline__ float bff(unsigned short u) {
    BU t; t.u = u; return __bfloat162float(t.b);
}

__device__ __forceinline__ void split_store(const float* src, int idx,
                                            __nv_bfloat16* dst, bool isA,
                                            float* inv, int* mn) {
    float v[16];
    const float4* p = (const float4*)(src + (size_t)idx * 16);
    float4 q0 = p[0], q1 = p[1], q2 = p[2], q3 = p[3];
    v[0]=q0.x; v[1]=q0.y; v[2]=q0.z; v[3]=q0.w;
    v[4]=q1.x; v[5]=q1.y; v[6]=q1.z; v[7]=q1.w;
    v[8]=q2.x; v[9]=q2.y; v[10]=q2.z; v[11]=q2.w;
    v[12]=q3.x; v[13]=q3.y; v[14]=q3.z; v[15]=q3.w;
    float s = 0.f;
#pragma unroll
    for (int d = 0; d < 16; d++) s += v[d] * v[d];
    inv[idx] = 1.0f / (1.0f - s);
    mn[idx]  = 0x7f800000;

    unsigned short hi[16], lo[16];
#pragma unroll
    for (int d = 0; d < 16; d++) {
        hi[d] = bfu(v[d]);
        lo[d] = bfu(v[d] - bff(hi[d]));
    }
    uint32_t w[32];
#pragma unroll
    for (int k = 0; k < 8; k++) {
        uint32_t hp = (uint32_t)hi[2*k] | ((uint32_t)hi[2*k+1] << 16);
        uint32_t lp = (uint32_t)lo[2*k] | ((uint32_t)lo[2*k+1] << 16);
        w[k]      = hp;
        w[8 + k]  = isA ? lp : hp;
        w[16 + k] = isA ? hp : lp;
    }
    if (isA) {
        unsigned short nh = bfu(s);
        unsigned short nl = bfu(s - bff(nh));
        unsigned short one = bfu(1.0f);
        w[24] = (uint32_t)nh | ((uint32_t)nl << 16);
        w[25] = (uint32_t)one | ((uint32_t)one << 16);
    } else {
        float m = -0.5f * s;
        unsigned short mh = bfu(m);
        unsigned short ml = bfu(m - bff(mh));
        unsigned short nhalf = bfu(-0.5f);
        w[24] = (uint32_t)nhalf | ((uint32_t)nhalf << 16);
        w[25] = (uint32_t)mh | ((uint32_t)ml << 16);
    }
#pragma unroll
    for (int k = 26; k < 32; k++) w[k] = 0u;

    uint4* d4 = (uint4*)(dst + (size_t)idx * 64);
#pragma unroll
    for (int c = 0; c < 8; c++)
        d4[c] = make_uint4(w[4*c], w[4*c+1], w[4*c+2], w[4*c+3]);
}

// blocks [0,64): X points; blocks [64,128): Y points
__global__ void prep_kernel(const float* __restrict__ X,
                            const float* __restrict__ Y, int N, int M) {
    int b = blockIdx.x;
    if (b == 0 && threadIdx.x == 0) g_done = 0;
    if (b < 64) {
        int idx = b * 256 + threadIdx.x;
        if (idx < N) split_store(X, idx, g_A, true,  g_invx, g_rowmin);
    } else {
        int idx = (b - 64) * 256 + threadIdx.x;
        if (idx < M) split_store(Y, idx, g_B, false, g_invy, g_colmin);
    }
}

// ---------------------------------------------------------------- pair kernel
__global__ void __launch_bounds__(256, 2) pair_mma_kernel() {
    __shared__ __align__(16) char sA[128 * 128];   // 128 rows x 128B (K=64 bf16)
    __shared__ __align__(16) char sB[128 * 128];
    __shared__ float s_nx[128], s_ny[128];
    __shared__ float rowpart[2][128];
    __shared__ float colpart[4][128];

    const int tid  = threadIdx.x;
    const int wid  = tid >> 5;
    const int lane = tid & 31;
    const int i0   = blockIdx.y * 128;
    const int j0   = blockIdx.x * 128;

    // ---- load tiles (SW128 swizzled)
    {
        const uint4* Ag = (const uint4*)g_A + (size_t)i0 * 8;
        const uint4* Bg = (const uint4*)g_B + (size_t)j0 * 8;
#pragma unroll
        for (int k = tid; k < 1024; k += 256) {
            int r = k >> 3, c = k & 7;
            *(uint4*)(sA + SMEM_SWZ(r * 128 + c * 16)) = Ag[k];
            *(uint4*)(sB + SMEM_SWZ(r * 128 + c * 16)) = Bg[k];
        }
    }
    if (tid < 128) {
        s_nx[tid] = -2.0f * g_invx[i0 + tid];
        s_ny[tid] = -2.0f * g_invy[j0 + tid];
    }
    __syncthreads();

    const uint32_t sAb = smem_u32(sA);
    const uint32_t sBb = smem_u32(sB);
    const int wr = wid & 3;          // warp row: 32 i-rows
    const int wc = wid >> 2;         // warp col: 64 j-cols
    const int lr = lane & 15;
    const int lc = lane >> 4;
    const float INF = __int_as_float(0x7f800000);

    // ---- A fragments hoisted out of the column-half loop
    uint32_t afr[4][2][4];
#pragma unroll
    for (int ks = 0; ks < 4; ks++)
#pragma unroll
        for (int mt = 0; mt < 2; mt++) {
            int row = 32*wr + 16*mt + lr;
            LDSM4(afr[ks][mt], sAb + SMEM_SWZ(row*128 + ks*32 + lc*16));
        }

    float nxv[4];
#pragma unroll
    for (int mt = 0; mt < 2; mt++)
#pragma unroll
        for (int rr = 0; rr < 2; rr++)
            nxv[2*mt+rr] = s_nx[32*wr + 16*mt + 8*rr + (lane >> 2)];

    float rmin[4] = {INF, INF, INF, INF};

#pragma unroll
    for (int h = 0; h < 2; h++) {   // 32-col halves of the warp's 64 cols
        float nyv[8];
#pragma unroll
        for (int nt = 0; nt < 4; nt++)
#pragma unroll
            for (int c = 0; c < 2; c++)
                nyv[2*nt+c] = s_ny[64*wc + 32*h + 8*nt + 2*(lane & 3) + c];

        float acc[2][4][4];
#pragma unroll
        for (int mt = 0; mt < 2; mt++)
#pragma unroll
            for (int nt = 0; nt < 4; nt++)
#pragma unroll
                for (int e = 0; e < 4; e++) acc[mt][nt][e] = 0.0f;

#pragma unroll
        for (int ks = 0; ks < 4; ks++) {
            uint32_t b[2][4];
#pragma unroll
            for (int np = 0; np < 2; np++) {
                int row = 64*wc + 32*h + 16*np + lr;
                LDSM4(b[np], sBb + SMEM_SWZ(row*128 + ks*32 + lc*16));
            }
#pragma unroll
            for (int mt = 0; mt < 2; mt++)
#pragma unroll
                for (int nt = 0; nt < 4; nt++) {
                    int np = nt >> 1, od = nt & 1;
                    MMA16816(acc[mt][nt], afr[ks][mt], b[np][od], b[np][od+2]);
                }
        }

        // ---- epilogue: 2 MUL + 2 MIN per pair (fma/alu dual-issue)
        float cmin[8];
#pragma unroll
        for (int k = 0; k < 8; k++) cmin[k] = INF;
#pragma unroll
        for (int mt = 0; mt < 2; mt++)
#pragma unroll
            for (int nt = 0; nt < 4; nt++) {
                float* c = acc[mt][nt];
                rmin[2*mt]   = fminf(rmin[2*mt],
                               fminf(c[0]*nyv[2*nt], c[1]*nyv[2*nt+1]));
                rmin[2*mt+1] = fminf(rmin[2*mt+1],
                               fminf(c[2]*nyv[2*nt], c[3]*nyv[2*nt+1]));
                cmin[2*nt]   = fminf(cmin[2*nt],
                               fminf(c[0]*nxv[2*mt], c[2]*nxv[2*mt+1]));
                cmin[2*nt+1] = fminf(cmin[2*nt+1],
                               fminf(c[1]*nxv[2*mt], c[3]*nxv[2*mt+1]));
            }

        // reduce col-mins across lanes sharing (lane&3): xor 4, 8, 16
#pragma unroll
        for (int k = 0; k < 8; k++) {
            float v = cmin[k];
            v = fminf(v, __shfl_xor_sync(0xffffffffu, v, 4));
            v = fminf(v, __shfl_xor_sync(0xffffffffu, v, 8));
            v = fminf(v, __shfl_xor_sync(0xffffffffu, v, 16));
            if (lane < 4)
                colpart[wr][64*wc + 32*h + 8*(k >> 1) + 2*lane + (k & 1)] = v;
        }
    }

    // reduce row-mins across lane&3: xor 1, 2
#pragma unroll
    for (int k = 0; k < 4; k++) {
        float v = rmin[k];
        v = fminf(v, __shfl_xor_sync(0xffffffffu, v, 1));
        v = fminf(v, __shfl_xor_sync(0xffffffffu, v, 2));
        if ((lane & 3) == 0)
            rowpart[wc][32*wr + 16*(k >> 1) + 8*(k & 1) + (lane >> 2)] = v;
    }
    __syncthreads();

    if (tid < 128) {
        float rv = fminf(rowpart[0][tid], rowpart[1][tid]);
        atomicMin(&g_rowmin[i0 + tid], __float_as_int(fmaxf(rv, 0.0f)));
        float cv = fminf(fminf(colpart[0][tid], colpart[1][tid]),
                         fminf(colpart[2][tid], colpart[3][tid]));
        atomicMin(&g_colmin[j0 + tid], __float_as_int(fmaxf(cv, 0.0f)));
    }
}

// ---------------------------------------------------------------- finalize
__global__ void finalize_kernel(int N, int M, float* out) {
    __shared__ float red[256];
    __shared__ int   lastFlag;
    int  b     = blockIdx.x;
    bool isRow = (b < 64);
    int  idx   = (isRow ? b : b - 64) * 256 + threadIdx.x;
    float val  = 0.0f;
    int   lim  = isRow ? N : M;
    if (idx < lim) {
        float m   = fmaxf(__int_as_float(isRow ? g_rowmin[idx] : g_colmin[idx]),
                          0.0f);
        float inv = isRow ? g_invx[idx] : g_invy[idx];
        float u   = fmaf(2.0f * m, inv, 1.0f);
        val       = logf(u + sqrtf(fmaxf(u * u - 1.0f, 0.0f)));
    }
    red[threadIdx.x] = val;
    __syncthreads();
    for (int s = 128; s > 0; s >>= 1) {
        if (threadIdx.x < s) red[threadIdx.x] += red[threadIdx.x + s];
        __syncthreads();
    }
    if (threadIdx.x == 0) {
        g_part[b] = red[0] * (isRow ? 1.0f / (float)N : 1.0f / (float)M);
        __threadfence();
        int t = atomicAdd(&g_done, 1);
        lastFlag = (t == 127);
    }
    __syncthreads();
    if (lastFlag) {
        red[threadIdx.x] = (threadIdx.x < 128) ? g_part[threadIdx.x] : 0.0f;
        __syncthreads();
        for (int s = 128; s > 0; s >>= 1) {
            if (threadIdx.x < s) red[threadIdx.x] += red[threadIdx.x + s];
            __syncthreads();
        }
        if (threadIdx.x == 0) out[0] = red[0];
    }
}

// ---------------------------------------------------------------- launch
extern "C" void kernel_launch(void* const* d_in, const int* in_sizes, int n_in,
                              void* d_out, int out_size) {
    const float* X = (const float*)d_in[0];
    const float* Y = (const float*)d_in[1];
    int N = in_sizes[0] / 16;
    int M = in_sizes[1] / 16;

    prep_kernel<<<128, 256>>>(X, Y, N, M);

    dim3 grid(M / 128, N / 128);
    pair_mma_kernel<<<grid, 256>>>();

    finalize_kernel<<<128, 256>>>(N, M, (float*)d_out);
}

// round 6
// speedup vs baseline: 1.4033x; 1.1864x over previous
#include <cuda_runtime.h>
#include <cuda_bf16.h>
#include <cstdint>

// ============================================================================
// Hyperbolic averaged Hausdorff loss via tensor-core mma.sync (bf16).
// (build targets plain sm_103: tcgen05 unavailable; legacy HMMA path)
//
// K=64 norm-fold GEMM (see R5): acc_ij = dot_ij - (xn_i + yn_j)/2.
// Row-min of acc*(-2invy_j), col-min of acc*(-2invx_i); arcosh at the end.
//
// R6: persistent-A sweep. Each CTA owns a 128-row i-block and sweeps 8
// B-tiles (one 1024-col j-chunk) with cp.async double buffering; A tile +
// fragments loaded once per sweep; ONE __syncthreads per tile (merged
// buffer-ready + colpart-staging barrier); row mins accumulate in registers
// across the sweep.
// ============================================================================

#define NPTS 16384
#define TILES_PER_SWEEP 8

__device__ float g_invx[NPTS], g_invy[NPTS];
__device__ int   g_rowmin[NPTS], g_colmin[NPTS];
__device__ float g_part[128];
__device__ int   g_done;
__device__ __nv_bfloat16 g_A[NPTS * 64];
__device__ __nv_bfloat16 g_B[NPTS * 64];

__device__ __forceinline__ uint32_t smem_u32(const void* p) {
    uint32_t a;
    asm("{ .reg .u64 t; cvta.to.shared.u64 t, %1; cvt.u32.u64 %0, t; }"
        : "=r"(a) : "l"(p));
    return a;
}
#define SMEM_SWZ(o) ((o) ^ ((((o) >> 3) & 0x70)))

#define CPASYNC16(dst, src) \
    asm volatile("cp.async.cg.shared.global [%0], [%1], 16;" \
                 :: "r"(dst), "l"(src))
#define CPCOMMIT() asm volatile("cp.async.commit_group;")
#define CPWAIT0()  asm volatile("cp.async.wait_group 0;")

#define LDSM4(r, addr)                                                      \
    asm volatile("ldmatrix.sync.aligned.m8n8.x4.shared.b16 "                \
                 "{%0,%1,%2,%3}, [%4];"                                     \
                 : "=r"((r)[0]), "=r"((r)[1]), "=r"((r)[2]), "=r"((r)[3])   \
                 : "r"(addr))

#define MMA16816(d, a, b0, b1)                                              \
    asm volatile("mma.sync.aligned.m16n8k16.row.col.f32.bf16.bf16.f32 "     \
                 "{%0,%1,%2,%3}, {%4,%5,%6,%7}, {%8,%9}, {%0,%1,%2,%3};"    \
                 : "+f"((d)[0]), "+f"((d)[1]), "+f"((d)[2]), "+f"((d)[3])   \
                 : "r"((a)[0]), "r"((a)[1]), "r"((a)[2]), "r"((a)[3]),      \
                   "r"(b0), "r"(b1))

// ---------------------------------------------------------------- smem layout
#define SM_A    0                       // 16384   (128 rows x 128B)
#define SM_B    16384                   // 2 x 16384
#define SM_NY   49152                   // 1024 x f32 = 4096 (-2*invy of chunk)
#define SM_COL  53248                   // 2 x 4 x 128 x f32 = 4096
#define SM_ROW  57344                   // 2 x 128 x f32 = 1024
#define SM_TOT  58368

// ---------------------------------------------------------------- prep kernel
union BU { __nv_bfloat16 b; unsigned short u; };
__device__ __forceinline__ unsigned short bfu(float x) {
    BU t; t.b = __float2bfloat16(x); return t.u;
}
__device__ __forceinline__ float bff(unsigned short u) {
    BU t; t.u = u; return __bfloat162float(t.b);
}

__device__ __forceinline__ void split_store(const float* src, int idx,
                                            __nv_bfloat16* dst, bool isA,
                                            float* inv, int* mn) {
    float v[16];
    const float4* p = (const float4*)(src + (size_t)idx * 16);
    float4 q0 = p[0], q1 = p[1], q2 = p[2], q3 = p[3];
    v[0]=q0.x; v[1]=q0.y; v[2]=q0.z; v[3]=q0.w;
    v[4]=q1.x; v[5]=q1.y; v[6]=q1.z; v[7]=q1.w;
    v[8]=q2.x; v[9]=q2.y; v[10]=q2.z; v[11]=q2.w;
    v[12]=q3.x; v[13]=q3.y; v[14]=q3.z; v[15]=q3.w;
    float s = 0.f;
#pragma unroll
    for (int d = 0; d < 16; d++) s += v[d] * v[d];
    inv[idx] = 1.0f / (1.0f - s);
    mn[idx]  = 0x7f800000;

    unsigned short hi[16], lo[16];
#pragma unroll
    for (int d = 0; d < 16; d++) {
        hi[d] = bfu(v[d]);
        lo[d] = bfu(v[d] - bff(hi[d]));
    }
    uint32_t w[32];
#pragma unroll
    for (int k = 0; k < 8; k++) {
        uint32_t hp = (uint32_t)hi[2*k] | ((uint32_t)hi[2*k+1] << 16);
        uint32_t lp = (uint32_t)lo[2*k] | ((uint32_t)lo[2*k+1] << 16);
        w[k]      = hp;
        w[8 + k]  = isA ? lp : hp;
        w[16 + k] = isA ? hp : lp;
    }
    if (isA) {
        unsigned short nh = bfu(s);
        unsigned short nl = bfu(s - bff(nh));
        unsigned short one = bfu(1.0f);
        w[24] = (uint32_t)nh | ((uint32_t)nl << 16);
        w[25] = (uint32_t)one | ((uint32_t)one << 16);
    } else {
        float m = -0.5f * s;
        unsigned short mh = bfu(m);
        unsigned short ml = bfu(m - bff(mh));
        unsigned short nhalf = bfu(-0.5f);
        w[24] = (uint32_t)nhalf | ((uint32_t)nhalf << 16);
        w[25] = (uint32_t)mh | ((uint32_t)ml << 16);
    }
#pragma unroll
    for (int k = 26; k < 32; k++) w[k] = 0u;

    uint4* d4 = (uint4*)(dst + (size_t)idx * 64);
#pragma unroll
    for (int c = 0; c < 8; c++)
        d4[c] = make_uint4(w[4*c], w[4*c+1], w[4*c+2], w[4*c+3]);
}

__global__ void prep_kernel(const float* __restrict__ X,
                            const float* __restrict__ Y, int N, int M) {
    int b = blockIdx.x;
    if (b == 0 && threadIdx.x == 0) g_done = 0;
    if (b < 64) {
        int idx = b * 256 + threadIdx.x;
        if (idx < N) split_store(X, idx, g_A, true,  g_invx, g_rowmin);
    } else {
        int idx = (b - 64) * 256 + threadIdx.x;
        if (idx < M) split_store(Y, idx, g_B, false, g_invy, g_colmin);
    }
}

// ---------------------------------------------------------------- pair kernel
__global__ void __launch_bounds__(256, 2) pair_mma_kernel() {
    extern __shared__ __align__(16) char smem[];
    const uint32_t sb = smem_u32(smem);

    const int tid  = threadIdx.x;
    const int wid  = tid >> 5;
    const int lane = tid & 31;
    const int i0   = blockIdx.y * 128;
    const int jc0  = blockIdx.x * 1024;          // chunk base column

    const int wr = wid & 3;
    const int wc = wid >> 2;
    const int lr = lane & 15;
    const int lc = lane >> 4;
    const float INF = __int_as_float(0x7f800000);

    const int cr = tid >> 3, cc = tid & 7;       // 16B-chunk coords (4/thread)
    const uint32_t swz0 = SMEM_SWZ(cr * 128 + cc * 16);
    const uint32_t swz1 = SMEM_SWZ((cr + 32) * 128 + cc * 16);
    const uint32_t swz2 = SMEM_SWZ((cr + 64) * 128 + cc * 16);
    const uint32_t swz3 = SMEM_SWZ((cr + 96) * 128 + cc * 16);
    const size_t   goff = (size_t)cr * 128 + cc * 16;

    // ---- prologue: async-copy A tile + B tile 0 (group 0)
    {
        const char* Ag = (const char*)g_A + (size_t)i0 * 128;
        CPASYNC16(sb + SM_A + swz0, Ag + goff);
        CPASYNC16(sb + SM_A + swz1, Ag + goff + 32 * 128);
        CPASYNC16(sb + SM_A + swz2, Ag + goff + 64 * 128);
        CPASYNC16(sb + SM_A + swz3, Ag + goff + 96 * 128);
        const char* Bg = (const char*)g_B + (size_t)jc0 * 128;
        CPASYNC16(sb + SM_B + swz0, Bg + goff);
        CPASYNC16(sb + SM_B + swz1, Bg + goff + 32 * 128);
        CPASYNC16(sb + SM_B + swz2, Bg + goff + 64 * 128);
        CPASYNC16(sb + SM_B + swz3, Bg + goff + 96 * 128);
        CPCOMMIT();
        // -2*invy for the whole chunk (plain shared stores)
        float4 w = ((const float4*)(g_invy + jc0))[tid];
        ((float4*)(smem + SM_NY))[tid] =
            make_float4(-2.f*w.x, -2.f*w.y, -2.f*w.z, -2.f*w.w);
    }

    // per-row constants straight from gmem (4 LDG, overlap the cp.async wait)
    float nxv[4];
#pragma unroll
    for (int mt = 0; mt < 2; mt++)
#pragma unroll
        for (int rr = 0; rr < 2; rr++)
            nxv[2*mt+rr] = -2.0f * g_invx[i0 + 32*wr + 16*mt + 8*rr + (lane >> 2)];

    CPWAIT0();
    __syncthreads();

    // ---- A fragments once per sweep
    uint32_t afr[4][2][4];
#pragma unroll
    for (int ks = 0; ks < 4; ks++)
#pragma unroll
        for (int mt = 0; mt < 2; mt++) {
            int row = 32*wr + 16*mt + lr;
            LDSM4(afr[ks][mt], sb + SM_A + SMEM_SWZ(row*128 + ks*32 + lc*16));
        }

    // prefetch B tile 1
    {
        const char* Bg = (const char*)g_B + (size_t)(jc0 + 128) * 128;
        uint32_t d = sb + SM_B + 16384;
        CPASYNC16(d + swz0, Bg + goff);
        CPASYNC16(d + swz1, Bg + goff + 32 * 128);
        CPASYNC16(d + swz2, Bg + goff + 64 * 128);
        CPASYNC16(d + swz3, Bg + goff + 96 * 128);
        CPCOMMIT();
    }

    const float* sNY = (const float*)(smem + SM_NY);
    float* colp = (float*)(smem + SM_COL);       // [2][4][128]
    float rmin[4] = {INF, INF, INF, INF};

#pragma unroll 1
    for (int t = 0; t < TILES_PER_SWEEP; t++) {
        if (t > 0) {
            CPWAIT0();
            __syncthreads();
            // prefetch tile t+1 into buffer (t+1)&1 (holds tile t-1, consumed)
            if (t + 1 < TILES_PER_SWEEP) {
                const char* Bg =
                    (const char*)g_B + (size_t)(jc0 + (t + 1) * 128) * 128;
                uint32_t d = sb + SM_B + ((t + 1) & 1) * 16384;
                CPASYNC16(d + swz0, Bg + goff);
                CPASYNC16(d + swz1, Bg + goff + 32 * 128);
                CPASYNC16(d + swz2, Bg + goff + 64 * 128);
                CPASYNC16(d + swz3, Bg + goff + 96 * 128);
                CPCOMMIT();
            }
            // col reduce + atomics for tile t-1
            if (tid < 128) {
                const float* cp0 = colp + ((t - 1) & 1) * 512;
                float cv = fminf(fminf(cp0[tid], cp0[128 + tid]),
                                 fminf(cp0[256 + tid], cp0[384 + tid]));
                atomicMin(&g_colmin[jc0 + (t - 1) * 128 + tid],
                          __float_as_int(fmaxf(cv, 0.0f)));
            }
        }

        const uint32_t sBb = sb + SM_B + (t & 1) * 16384;
        float* cpw = colp + (t & 1) * 512;
        const int jt = t * 128;

#pragma unroll
        for (int h = 0; h < 2; h++) {
            float nyv[8];
#pragma unroll
            for (int nt = 0; nt < 4; nt++)
#pragma unroll
                for (int c = 0; c < 2; c++)
                    nyv[2*nt+c] = sNY[jt + 64*wc + 32*h + 8*nt + 2*(lane & 3) + c];

            float acc[2][4][4];
#pragma unroll
            for (int mt = 0; mt < 2; mt++)
#pragma unroll
                for (int nt = 0; nt < 4; nt++)
#pragma unroll
                    for (int e = 0; e < 4; e++) acc[mt][nt][e] = 0.0f;

#pragma unroll
            for (int ks = 0; ks < 4; ks++) {
                uint32_t b[2][4];
#pragma unroll
                for (int np = 0; np < 2; np++) {
                    int row = 64*wc + 32*h + 16*np + lr;
                    LDSM4(b[np], sBb + SMEM_SWZ(row*128 + ks*32 + lc*16));
                }
#pragma unroll
                for (int mt = 0; mt < 2; mt++)
#pragma unroll
                    for (int nt = 0; nt < 4; nt++) {
                        int np = nt >> 1, od = nt & 1;
                        MMA16816(acc[mt][nt], afr[ks][mt], b[np][od], b[np][od+2]);
                    }
            }

            // epilogue: 2 MUL + 2 MIN per pair
            float cmin[8];
#pragma unroll
            for (int k = 0; k < 8; k++) cmin[k] = INF;
#pragma unroll
            for (int mt = 0; mt < 2; mt++)
#pragma unroll
                for (int nt = 0; nt < 4; nt++) {
                    float* c = acc[mt][nt];
                    rmin[2*mt]   = fminf(rmin[2*mt],
                                   fminf(c[0]*nyv[2*nt], c[1]*nyv[2*nt+1]));
                    rmin[2*mt+1] = fminf(rmin[2*mt+1],
                                   fminf(c[2]*nyv[2*nt], c[3]*nyv[2*nt+1]));
                    cmin[2*nt]   = fminf(cmin[2*nt],
                                   fminf(c[0]*nxv[2*mt], c[2]*nxv[2*mt+1]));
                    cmin[2*nt+1] = fminf(cmin[2*nt+1],
                                   fminf(c[1]*nxv[2*mt], c[3]*nxv[2*mt+1]));
                }

            // col-min partial: reduce across row-lanes, lanes 0..3 store
#pragma unroll
            for (int k = 0; k < 8; k++) {
                float v = cmin[k];
                v = fminf(v, __shfl_xor_sync(0xffffffffu, v, 4));
                v = fminf(v, __shfl_xor_sync(0xffffffffu, v, 8));
                v = fminf(v, __shfl_xor_sync(0xffffffffu, v, 16));
                if (lane < 4)
                    cpw[wr*128 + 64*wc + 32*h + 8*(k >> 1) + 2*lane + (k & 1)] = v;
            }
        }
    }

    // ---- epilogue of sweep: last tile's col mins + row mins
    __syncthreads();
    if (tid < 128) {
        const float* cp0 = colp + ((TILES_PER_SWEEP - 1) & 1) * 512;
        float cv = fminf(fminf(cp0[tid], cp0[128 + tid]),
                         fminf(cp0[256 + tid], cp0[384 + tid]));
        atomicMin(&g_colmin[jc0 + (TILES_PER_SWEEP - 1) * 128 + tid],
                  __float_as_int(fmaxf(cv, 0.0f)));
    }

    float* rowp = (float*)(smem + SM_ROW);       // [2][128]
#pragma unroll
    for (int k = 0; k < 4; k++) {
        float v = rmin[k];
        v = fminf(v, __shfl_xor_sync(0xffffffffu, v, 1));
        v = fminf(v, __shfl_xor_sync(0xffffffffu, v, 2));
        if ((lane & 3) == 0)
            rowp[wc*128 + 32*wr + 16*(k >> 1) + 8*(k & 1) + (lane >> 2)] = v;
    }
    __syncthreads();
    if (tid < 128) {
        float rv = fminf(rowp[tid], rowp[128 + tid]);
        atomicMin(&g_rowmin[i0 + tid], __float_as_int(fmaxf(rv, 0.0f)));
    }
}

// ---------------------------------------------------------------- finalize
__global__ void finalize_kernel(int N, int M, float* out) {
    __shared__ float red[256];
    __shared__ int   lastFlag;
    int  b     = blockIdx.x;
    bool isRow = (b < 64);
    int  idx   = (isRow ? b : b - 64) * 256 + threadIdx.x;
    float val  = 0.0f;
    int   lim  = isRow ? N : M;
    if (idx < lim) {
        float m   = fmaxf(__int_as_float(isRow ? g_rowmin[idx] : g_colmin[idx]),
                          0.0f);
        float inv = isRow ? g_invx[idx] : g_invy[idx];
        float u   = fmaf(2.0f * m, inv, 1.0f);
        val       = logf(u + sqrtf(fmaxf(u * u - 1.0f, 0.0f)));
    }
    red[threadIdx.x] = val;
    __syncthreads();
    for (int s = 128; s > 0; s >>= 1) {
        if (threadIdx.x < s) red[threadIdx.x] += red[threadIdx.x + s];
        __syncthreads();
    }
    if (threadIdx.x == 0) {
        g_part[b] = red[0] * (isRow ? 1.0f / (float)N : 1.0f / (float)M);
        __threadfence();
        int t = atomicAdd(&g_done, 1);
        lastFlag = (t == 127);
    }
    __syncthreads();
    if (lastFlag) {
        red[threadIdx.x] = (threadIdx.x < 128) ? g_part[threadIdx.x] : 0.0f;
        __syncthreads();
        for (int s = 128; s > 0; s >>= 1) {
            if (threadIdx.x < s) red[threadIdx.x] += red[threadIdx.x + s];
            __syncthreads();
        }
        if (threadIdx.x == 0) out[0] = red[0];
    }
}

// ---------------------------------------------------------------- launch
extern "C" void kernel_launch(void* const* d_in, const int* in_sizes, int n_in,
                              void* d_out, int out_size) {
    const float* X = (const float*)d_in[0];
    const float* Y = (const float*)d_in[1];
    int N = in_sizes[0] / 16;
    int M = in_sizes[1] / 16;

    static int configured = 0;
    if (!configured) {
        cudaFuncSetAttribute(pair_mma_kernel,
                             cudaFuncAttributeMaxDynamicSharedMemorySize,
                             SM_TOT);
        configured = 1;
    }

    prep_kernel<<<128, 256>>>(X, Y, N, M);

    dim3 grid(M / 1024, N / 128);
    pair_mma_kernel<<<grid, 256, SM_TOT>>>();

    finalize_kernel<<<128, 256>>>(N, M, (float*)d_out);
}

// round 7
// speedup vs baseline: 1.4214x; 1.0129x over previous
#include <cuda_runtime.h>
#include <cuda_bf16.h>
#include <cstdint>

// ============================================================================
// Hyperbolic averaged Hausdorff loss via tensor-core mma.sync (bf16).
// (build targets plain sm_103: tcgen05 unavailable; legacy HMMA path)
//
// K=64 norm-fold GEMM: acc_ij = dot_ij - (xn_i + yn_j)/2 (bf16 hi/lo split).
// Row-min of acc*(-2invy_j), col-min of acc*(-2invx_i); arcosh at the end.
//
// R7: col-min reduction via reduce-scatter shuffles (12 shfl vs 24) with each
// lane ending as unique owner of one column -> direct 32-lane atomicMin, no
// smem staging, no second reduction pass. One barrier per tile (buffer swap).
// ============================================================================

#define NPTS 16384
#define TILES_PER_SWEEP 8

__device__ float g_invx[NPTS], g_invy[NPTS];
__device__ int   g_rowmin[NPTS], g_colmin[NPTS];
__device__ float g_part[128];
__device__ int   g_done;
__device__ __nv_bfloat16 g_A[NPTS * 64];
__device__ __nv_bfloat16 g_B[NPTS * 64];

__device__ __forceinline__ uint32_t smem_u32(const void* p) {
    uint32_t a;
    asm("{ .reg .u64 t; cvta.to.shared.u64 t, %1; cvt.u32.u64 %0, t; }"
        : "=r"(a) : "l"(p));
    return a;
}
#define SMEM_SWZ(o) ((o) ^ ((((o) >> 3) & 0x70)))

#define CPASYNC16(dst, src) \
    asm volatile("cp.async.cg.shared.global [%0], [%1], 16;" \
                 :: "r"(dst), "l"(src))
#define CPCOMMIT() asm volatile("cp.async.commit_group;")
#define CPWAIT0()  asm volatile("cp.async.wait_group 0;")

#define LDSM4(r, addr)                                                      \
    asm volatile("ldmatrix.sync.aligned.m8n8.x4.shared.b16 "                \
                 "{%0,%1,%2,%3}, [%4];"                                     \
                 : "=r"((r)[0]), "=r"((r)[1]), "=r"((r)[2]), "=r"((r)[3])   \
                 : "r"(addr))

#define MMA16816(d, a, b0, b1)                                              \
    asm volatile("mma.sync.aligned.m16n8k16.row.col.f32.bf16.bf16.f32 "     \
                 "{%0,%1,%2,%3}, {%4,%5,%6,%7}, {%8,%9}, {%0,%1,%2,%3};"    \
                 : "+f"((d)[0]), "+f"((d)[1]), "+f"((d)[2]), "+f"((d)[3])   \
                 : "r"((a)[0]), "r"((a)[1]), "r"((a)[2]), "r"((a)[3]),      \
                   "r"(b0), "r"(b1))

// ---------------------------------------------------------------- smem layout
#define SM_A    0                       // 16384   (128 rows x 128B)
#define SM_B    16384                   // 2 x 16384 -> ends 49152
#define SM_NY   49152                   // 1024 x f32 = 4096 (-2*invy of chunk)
#define SM_ROW  53248                   // 2 x 128 x f32 = 1024
#define SM_TOT  54272

// ---------------------------------------------------------------- prep kernel
union BU { __nv_bfloat16 b; unsigned short u; };
__device__ __forceinline__ unsigned short bfu(float x) {
    BU t; t.b = __float2bfloat16(x); return t.u;
}
__device__ __forceinline__ float bff(unsigned short u) {
    BU t; t.u = u; return __bfloat162float(t.b);
}

__device__ __forceinline__ void split_store(const float* src, int idx,
                                            __nv_bfloat16* dst, bool isA,
                                            float* inv, int* mn) {
    float v[16];
    const float4* p = (const float4*)(src + (size_t)idx * 16);
    float4 q0 = p[0], q1 = p[1], q2 = p[2], q3 = p[3];
    v[0]=q0.x; v[1]=q0.y; v[2]=q0.z; v[3]=q0.w;
    v[4]=q1.x; v[5]=q1.y; v[6]=q1.z; v[7]=q1.w;
    v[8]=q2.x; v[9]=q2.y; v[10]=q2.z; v[11]=q2.w;
    v[12]=q3.x; v[13]=q3.y; v[14]=q3.z; v[15]=q3.w;
    float s = 0.f;
#pragma unroll
    for (int d = 0; d < 16; d++) s += v[d] * v[d];
    inv[idx] = 1.0f / (1.0f - s);
    mn[idx]  = 0x7f800000;

    unsigned short hi[16], lo[16];
#pragma unroll
    for (int d = 0; d < 16; d++) {
        hi[d] = bfu(v[d]);
        lo[d] = bfu(v[d] - bff(hi[d]));
    }
    uint32_t w[32];
#pragma unroll
    for (int k = 0; k < 8; k++) {
        uint32_t hp = (uint32_t)hi[2*k] | ((uint32_t)hi[2*k+1] << 16);
        uint32_t lp = (uint32_t)lo[2*k] | ((uint32_t)lo[2*k+1] << 16);
        w[k]      = hp;
        w[8 + k]  = isA ? lp : hp;
        w[16 + k] = isA ? hp : lp;
    }
    if (isA) {
        unsigned short nh = bfu(s);
        unsigned short nl = bfu(s - bff(nh));
        unsigned short one = bfu(1.0f);
        w[24] = (uint32_t)nh | ((uint32_t)nl << 16);
        w[25] = (uint32_t)one | ((uint32_t)one << 16);
    } else {
        float m = -0.5f * s;
        unsigned short mh = bfu(m);
        unsigned short ml = bfu(m - bff(mh));
        unsigned short nhalf = bfu(-0.5f);
        w[24] = (uint32_t)nhalf | ((uint32_t)nhalf << 16);
        w[25] = (uint32_t)mh | ((uint32_t)ml << 16);
    }
#pragma unroll
    for (int k = 26; k < 32; k++) w[k] = 0u;

    uint4* d4 = (uint4*)(dst + (size_t)idx * 64);
#pragma unroll
    for (int c = 0; c < 8; c++)
        d4[c] = make_uint4(w[4*c], w[4*c+1], w[4*c+2], w[4*c+3]);
}

__global__ void prep_kernel(const float* __restrict__ X,
                            const float* __restrict__ Y, int N, int M) {
    int b = blockIdx.x;
    if (b == 0 && threadIdx.x == 0) g_done = 0;
    if (b < 64) {
        int idx = b * 256 + threadIdx.x;
        if (idx < N) split_store(X, idx, g_A, true,  g_invx, g_rowmin);
    } else {
        int idx = (b - 64) * 256 + threadIdx.x;
        if (idx < M) split_store(Y, idx, g_B, false, g_invy, g_colmin);
    }
}

// ---------------------------------------------------------------- pair kernel
__global__ void __launch_bounds__(256, 2) pair_mma_kernel() {
    extern __shared__ __align__(16) char smem[];
    const uint32_t sb = smem_u32(smem);

    const int tid  = threadIdx.x;
    const int wid  = tid >> 5;
    const int lane = tid & 31;
    const int i0   = blockIdx.y * 128;
    const int jc0  = blockIdx.x * 1024;          // chunk base column

    const int wr = wid & 3;
    const int wc = wid >> 2;
    const int lr = lane & 15;
    const int lc = lane >> 4;
    const float INF = __int_as_float(0x7f800000);

    const int cr = tid >> 3, cc = tid & 7;       // 16B-chunk coords (4/thread)
    const uint32_t swz0 = SMEM_SWZ(cr * 128 + cc * 16);
    const uint32_t swz1 = SMEM_SWZ((cr + 32) * 128 + cc * 16);
    const uint32_t swz2 = SMEM_SWZ((cr + 64) * 128 + cc * 16);
    const uint32_t swz3 = SMEM_SWZ((cr + 96) * 128 + cc * 16);
    const size_t   goff = (size_t)cr * 128 + cc * 16;

    // ---- prologue: async-copy A tile + B tile 0
    {
        const char* Ag = (const char*)g_A + (size_t)i0 * 128;
        CPASYNC16(sb + SM_A + swz0, Ag + goff);
        CPASYNC16(sb + SM_A + swz1, Ag + goff + 32 * 128);
        CPASYNC16(sb + SM_A + swz2, Ag + goff + 64 * 128);
        CPASYNC16(sb + SM_A + swz3, Ag + goff + 96 * 128);
        const char* Bg = (const char*)g_B + (size_t)jc0 * 128;
        CPASYNC16(sb + SM_B + swz0, Bg + goff);
        CPASYNC16(sb + SM_B + swz1, Bg + goff + 32 * 128);
        CPASYNC16(sb + SM_B + swz2, Bg + goff + 64 * 128);
        CPASYNC16(sb + SM_B + swz3, Bg + goff + 96 * 128);
        CPCOMMIT();
        float4 w = ((const float4*)(g_invy + jc0))[tid];
        ((float4*)(smem + SM_NY))[tid] =
            make_float4(-2.f*w.x, -2.f*w.y, -2.f*w.z, -2.f*w.w);
    }

    float nxv[4];
#pragma unroll
    for (int mt = 0; mt < 2; mt++)
#pragma unroll
        for (int rr = 0; rr < 2; rr++)
            nxv[2*mt+rr] = -2.0f * g_invx[i0 + 32*wr + 16*mt + 8*rr + (lane >> 2)];

    CPWAIT0();
    __syncthreads();

    // ---- A fragments once per sweep
    uint32_t afr[4][2][4];
#pragma unroll
    for (int ks = 0; ks < 4; ks++)
#pragma unroll
        for (int mt = 0; mt < 2; mt++) {
            int row = 32*wr + 16*mt + lr;
            LDSM4(afr[ks][mt], sb + SM_A + SMEM_SWZ(row*128 + ks*32 + lc*16));
        }

    // prefetch B tile 1
    {
        const char* Bg = (const char*)g_B + (size_t)(jc0 + 128) * 128;
        uint32_t d = sb + SM_B + 16384;
        CPASYNC16(d + swz0, Bg + goff);
        CPASYNC16(d + swz1, Bg + goff + 32 * 128);
        CPASYNC16(d + swz2, Bg + goff + 64 * 128);
        CPASYNC16(d + swz3, Bg + goff + 96 * 128);
        CPCOMMIT();
    }

    const float* sNY = (const float*)(smem + SM_NY);
    float rmin[4] = {INF, INF, INF, INF};

    const int b16 = (lane >> 4) & 1;
    const int b8  = (lane >> 3) & 1;
    const int b4  = (lane >> 2) & 1;
    // column owned by this lane after reduce-scatter (within 32-col half)
    const int ownCol = 8 * (2 * b16 + b8) + 2 * (lane & 3) + b4;

#pragma unroll 1
    for (int t = 0; t < TILES_PER_SWEEP; t++) {
        if (t > 0) {
            CPWAIT0();
            __syncthreads();
            if (t + 1 < TILES_PER_SWEEP) {
                const char* Bg =
                    (const char*)g_B + (size_t)(jc0 + (t + 1) * 128) * 128;
                uint32_t d = sb + SM_B + ((t + 1) & 1) * 16384;
                CPASYNC16(d + swz0, Bg + goff);
                CPASYNC16(d + swz1, Bg + goff + 32 * 128);
                CPASYNC16(d + swz2, Bg + goff + 64 * 128);
                CPASYNC16(d + swz3, Bg + goff + 96 * 128);
                CPCOMMIT();
            }
        }

        const uint32_t sBb = sb + SM_B + (t & 1) * 16384;
        const int jt = t * 128;

#pragma unroll
        for (int h = 0; h < 2; h++) {
            float nyv[8];
#pragma unroll
            for (int nt = 0; nt < 4; nt++)
#pragma unroll
                for (int c = 0; c < 2; c++)
                    nyv[2*nt+c] = sNY[jt + 64*wc + 32*h + 8*nt + 2*(lane & 3) + c];

            float acc[2][4][4];
#pragma unroll
            for (int mt = 0; mt < 2; mt++)
#pragma unroll
                for (int nt = 0; nt < 4; nt++)
#pragma unroll
                    for (int e = 0; e < 4; e++) acc[mt][nt][e] = 0.0f;

#pragma unroll
            for (int ks = 0; ks < 4; ks++) {
                uint32_t b[2][4];
#pragma unroll
                for (int np = 0; np < 2; np++) {
                    int row = 64*wc + 32*h + 16*np + lr;
                    LDSM4(b[np], sBb + SMEM_SWZ(row*128 + ks*32 + lc*16));
                }
#pragma unroll
                for (int mt = 0; mt < 2; mt++)
#pragma unroll
                    for (int nt = 0; nt < 4; nt++) {
                        int np = nt >> 1, od = nt & 1;
                        MMA16816(acc[mt][nt], afr[ks][mt], b[np][od], b[np][od+2]);
                    }
            }

            // epilogue: 2 MUL + 2 MIN per pair
            float v[8];
#pragma unroll
            for (int k = 0; k < 8; k++) v[k] = INF;
#pragma unroll
            for (int mt = 0; mt < 2; mt++)
#pragma unroll
                for (int nt = 0; nt < 4; nt++) {
                    float* c = acc[mt][nt];
                    rmin[2*mt]   = fminf(rmin[2*mt],
                                   fminf(c[0]*nyv[2*nt], c[1]*nyv[2*nt+1]));
                    rmin[2*mt+1] = fminf(rmin[2*mt+1],
                                   fminf(c[2]*nyv[2*nt], c[3]*nyv[2*nt+1]));
                    v[2*nt]   = fminf(v[2*nt],
                                fminf(c[0]*nxv[2*mt], c[2]*nxv[2*mt+1]));
                    v[2*nt+1] = fminf(v[2*nt+1],
                                fminf(c[1]*nxv[2*mt], c[3]*nxv[2*mt+1]));
                }

            // ---- reduce-scatter col mins across the 8 duplicate lanes
            // level 1 (mask 16): keep 0..3 on b16=0, 4..7 on b16=1
#pragma unroll
            for (int q = 0; q < 4; q++) {
                float x = b16 ? v[q] : v[q + 4];
                float r = __shfl_xor_sync(0xffffffffu, x, 16);
                if (b16) v[q + 4] = fminf(v[q + 4], r);
                else     v[q]     = fminf(v[q], r);
            }
            // level 2 (mask 8): within each quad keep first/last 2
#pragma unroll
            for (int g = 0; g < 8; g += 4)
#pragma unroll
                for (int q = 0; q < 2; q++) {
                    float x = b8 ? v[g + q] : v[g + q + 2];
                    float r = __shfl_xor_sync(0xffffffffu, x, 8);
                    if (b8) v[g + q + 2] = fminf(v[g + q + 2], r);
                    else    v[g + q]     = fminf(v[g + q], r);
                }
            // level 3 (mask 4): within each pair keep one
#pragma unroll
            for (int g = 0; g < 8; g += 2) {
                float x = b4 ? v[g] : v[g + 1];
                float r = __shfl_xor_sync(0xffffffffu, x, 4);
                if (b4) v[g + 1] = fminf(v[g + 1], r);
                else    v[g]     = fminf(v[g], r);
            }
            float owned = b16 ? (b8 ? (b4 ? v[7] : v[6]) : (b4 ? v[5] : v[4]))
                              : (b8 ? (b4 ? v[3] : v[2]) : (b4 ? v[1] : v[0]));
            atomicMin(&g_colmin[jc0 + jt + 64*wc + 32*h + ownCol],
                      __float_as_int(fmaxf(owned, 0.0f)));
        }
    }

    // ---- sweep epilogue: row mins
    float* rowp = (float*)(smem + SM_ROW);       // [2][128]
#pragma unroll
    for (int k = 0; k < 4; k++) {
        float v = rmin[k];
        v = fminf(v, __shfl_xor_sync(0xffffffffu, v, 1));
        v = fminf(v, __shfl_xor_sync(0xffffffffu, v, 2));
        if ((lane & 3) == 0)
            rowp[wc*128 + 32*wr + 16*(k >> 1) + 8*(k & 1) + (lane >> 2)] = v;
    }
    __syncthreads();
    if (tid < 128) {
        float rv = fminf(rowp[tid], rowp[128 + tid]);
        atomicMin(&g_rowmin[i0 + tid], __float_as_int(fmaxf(rv, 0.0f)));
    }
}

// ---------------------------------------------------------------- finalize
__global__ void finalize_kernel(int N, int M, float* out) {
    __shared__ float red[256];
    __shared__ int   lastFlag;
    int  b     = blockIdx.x;
    bool isRow = (b < 64);
    int  idx   = (isRow ? b : b - 64) * 256 + threadIdx.x;
    float val  = 0.0f;
    int   lim  = isRow ? N : M;
    if (idx < lim) {
        float m   = fmaxf(__int_as_float(isRow ? g_rowmin[idx] : g_colmin[idx]),
                          0.0f);
        float inv = isRow ? g_invx[idx] : g_invy[idx];
        float u   = fmaf(2.0f * m, inv, 1.0f);
        val       = logf(u + sqrtf(fmaxf(u * u - 1.0f, 0.0f)));
    }
    red[threadIdx.x] = val;
    __syncthreads();
    for (int s = 128; s > 0; s >>= 1) {
        if (threadIdx.x < s) red[threadIdx.x] += red[threadIdx.x + s];
        __syncthreads();
    }
    if (threadIdx.x == 0) {
        g_part[b] = red[0] * (isRow ? 1.0f / (float)N : 1.0f / (float)M);
        __threadfence();
        int t = atomicAdd(&g_done, 1);
        lastFlag = (t == 127);
    }
    __syncthreads();
    if (lastFlag) {
        red[threadIdx.x] = (threadIdx.x < 128) ? g_part[threadIdx.x] : 0.0f;
        __syncthreads();
        for (int s = 128; s > 0; s >>= 1) {
            if (threadIdx.x < s) red[threadIdx.x] += red[threadIdx.x + s];
            __syncthreads();
        }
        if (threadIdx.x == 0) out[0] = red[0];
    }
}

// ---------------------------------------------------------------- launch
extern "C" void kernel_launch(void* const* d_in, const int* in_sizes, int n_in,
                              void* d_out, int out_size) {
    const float* X = (const float*)d_in[0];
    const float* Y = (const float*)d_in[1];
    int N = in_sizes[0] / 16;
    int M = in_sizes[1] / 16;

    static int configured = 0;
    if (!configured) {
        cudaFuncSetAttribute(pair_mma_kernel,
                             cudaFuncAttributeMaxDynamicSharedMemorySize,
                             SM_TOT);
        configured = 1;
    }

    prep_kernel<<<128, 256>>>(X, Y, N, M);

    dim3 grid(M / 1024, N / 128);
    pair_mma_kernel<<<grid, 256, SM_TOT>>>();

    finalize_kernel<<<128, 256>>>(N, M, (float*)d_out);
}